// round 1
// baseline (speedup 1.0000x reference)
#include <cuda_runtime.h>

// Problem constants (fixed shapes from setup_inputs)
#define T_TOKENS 16384   // 4 * 4096
#define H_DIM    1024
#define M_DIM    512     // H/2
#define E_NUM    8
#define D_DIM    1024

// Scratch (static device globals; no allocations allowed)
__device__ float g_h[T_TOKENS * M_DIM];       // router hidden activations (32 MB)
__device__ int   g_top[T_TOKENS];             // argmax expert per token
__device__ int   g_counts[E_NUM];
__device__ int   g_offsets[E_NUM + 1];
__device__ int   g_cursor[E_NUM];
__device__ int   g_perm[T_TOKENS];            // tokens grouped by expert

// ---------------------------------------------------------------------------
// K0: reset per-launch state (graph replays reuse device globals)
// ---------------------------------------------------------------------------
__global__ void k_zero() {
    if (threadIdx.x < E_NUM) g_counts[threadIdx.x] = 0;
}

// ---------------------------------------------------------------------------
// K1: h = relu(X @ w1 + b1)   [16384 x 1024] @ [1024 x 512]
// 128x128 tile, BK=8, 256 threads, 8x8 per thread, fp32
// ---------------------------------------------------------------------------
__global__ __launch_bounds__(256) void k_gemm1(const float* __restrict__ X,
                                               const float* __restrict__ W,
                                               const float* __restrict__ b1) {
    __shared__ float As[8][128];
    __shared__ float Bs[8][128];
    const int tid = threadIdx.x;
    const int tx = tid & 15, ty = tid >> 4;
    const int rowBase = blockIdx.x * 128;
    const int colBase = blockIdx.y * 128;
    const int aRow = tid >> 1, aK = (tid & 1) * 4;
    const int bRow = tid >> 5, bCol = (tid & 31) * 4;

    float acc[8][8] = {};
    for (int k0 = 0; k0 < H_DIM; k0 += 8) {
        float4 av = *(const float4*)&X[(size_t)(rowBase + aRow) * H_DIM + k0 + aK];
        As[aK + 0][aRow] = av.x;
        As[aK + 1][aRow] = av.y;
        As[aK + 2][aRow] = av.z;
        As[aK + 3][aRow] = av.w;
        *(float4*)&Bs[bRow][bCol] =
            *(const float4*)&W[(size_t)(k0 + bRow) * M_DIM + colBase + bCol];
        __syncthreads();
#pragma unroll
        for (int kk = 0; kk < 8; kk++) {
            float a[8], bb[8];
            *(float4*)&a[0]  = *(const float4*)&As[kk][ty * 8];
            *(float4*)&a[4]  = *(const float4*)&As[kk][ty * 8 + 4];
            *(float4*)&bb[0] = *(const float4*)&Bs[kk][tx * 8];
            *(float4*)&bb[4] = *(const float4*)&Bs[kk][tx * 8 + 4];
#pragma unroll
            for (int i = 0; i < 8; i++)
#pragma unroll
                for (int j = 0; j < 8; j++)
                    acc[i][j] += a[i] * bb[j];
        }
        __syncthreads();
    }
#pragma unroll
    for (int i = 0; i < 8; i++) {
        const int r = rowBase + ty * 8 + i;
#pragma unroll
        for (int j = 0; j < 8; j++) {
            const int c = colBase + tx * 8 + j;
            float v = acc[i][j] + b1[c];
            g_h[(size_t)r * M_DIM + c] = v > 0.f ? v : 0.f;
        }
    }
}

// ---------------------------------------------------------------------------
// K2: scores = h @ w2 + b2 ; top = argmax(scores) ; histogram counts
// One warp per token.
// ---------------------------------------------------------------------------
__global__ __launch_bounds__(256) void k_route(const float* __restrict__ w2,
                                               const float* __restrict__ b2) {
    __shared__ float s_w2[M_DIM * E_NUM];  // 16 KB
    for (int i = threadIdx.x; i < M_DIM * E_NUM; i += 256) s_w2[i] = w2[i];
    __syncthreads();

    const int warp = threadIdx.x >> 5, lane = threadIdx.x & 31;
    const int t = blockIdx.x * 8 + warp;
    float acc[E_NUM] = {};
    const float* hrow = &g_h[(size_t)t * M_DIM];
    for (int m = lane; m < M_DIM; m += 32) {
        const float hv = hrow[m];
#pragma unroll
        for (int e = 0; e < E_NUM; e++) acc[e] += hv * s_w2[m * E_NUM + e];
    }
#pragma unroll
    for (int e = 0; e < E_NUM; e++) {
        float v = acc[e];
#pragma unroll
        for (int off = 16; off > 0; off >>= 1) v += __shfl_down_sync(0xffffffffu, v, off);
        acc[e] = v;
    }
    if (lane == 0) {
        float best = acc[0] + b2[0];
        int bi = 0;
#pragma unroll
        for (int e = 1; e < E_NUM; e++) {
            const float v = acc[e] + b2[e];
            if (v > best) { best = v; bi = e; }  // first-max tie rule (matches jnp.argmax)
        }
        g_top[t] = bi;
        atomicAdd(&g_counts[bi], 1);
    }
}

// ---------------------------------------------------------------------------
// K3: exclusive scan over the 8 expert counts
// ---------------------------------------------------------------------------
__global__ void k_scan() {
    if (threadIdx.x == 0) {
        int off = 0;
        for (int e = 0; e < E_NUM; e++) {
            g_offsets[e] = off;
            g_cursor[e]  = off;
            off += g_counts[e];
        }
        g_offsets[E_NUM] = off;
    }
}

// ---------------------------------------------------------------------------
// K4: scatter token ids into per-expert contiguous lists
// ---------------------------------------------------------------------------
__global__ void k_scatter() {
    const int t = blockIdx.x * blockDim.x + threadIdx.x;
    if (t < T_TOKENS) {
        const int e = g_top[t];
        const int pos = atomicAdd(&g_cursor[e], 1);
        g_perm[pos] = t;
    }
}

// ---------------------------------------------------------------------------
// K5: grouped expert GEMM: out[t] = X[t] @ expert_W[e] + expert_b[e]
// grid: (token tiles, d tiles, experts). Gathered A rows, scattered stores.
// ---------------------------------------------------------------------------
__global__ __launch_bounds__(256) void k_expert(const float* __restrict__ X,
                                                const float* __restrict__ eW,
                                                const float* __restrict__ eb,
                                                float* __restrict__ out) {
    const int e = blockIdx.z;
    const int off = g_offsets[e];
    const int n = g_offsets[e + 1] - off;
    const int rowBase = blockIdx.x * 128;
    if (rowBase >= n) return;

    __shared__ float As[8][128];
    __shared__ float Bs[8][128];
    __shared__ int s_tok[128];

    const int tid = threadIdx.x;
    if (tid < 128) {
        const int m = rowBase + tid;
        s_tok[tid] = g_perm[off + (m < n ? m : 0)];
    }
    __syncthreads();

    const int tx = tid & 15, ty = tid >> 4;
    const int colBase = blockIdx.y * 128;
    const int aRow = tid >> 1, aK = (tid & 1) * 4;
    const int bRow = tid >> 5, bCol = (tid & 31) * 4;
    const float* W = eW + (size_t)e * H_DIM * D_DIM;
    const int tA = s_tok[aRow];

    float acc[8][8] = {};
    for (int k0 = 0; k0 < H_DIM; k0 += 8) {
        float4 av = *(const float4*)&X[(size_t)tA * H_DIM + k0 + aK];
        As[aK + 0][aRow] = av.x;
        As[aK + 1][aRow] = av.y;
        As[aK + 2][aRow] = av.z;
        As[aK + 3][aRow] = av.w;
        *(float4*)&Bs[bRow][bCol] =
            *(const float4*)&W[(size_t)(k0 + bRow) * D_DIM + colBase + bCol];
        __syncthreads();
#pragma unroll
        for (int kk = 0; kk < 8; kk++) {
            float a[8], bb[8];
            *(float4*)&a[0]  = *(const float4*)&As[kk][ty * 8];
            *(float4*)&a[4]  = *(const float4*)&As[kk][ty * 8 + 4];
            *(float4*)&bb[0] = *(const float4*)&Bs[kk][tx * 8];
            *(float4*)&bb[4] = *(const float4*)&Bs[kk][tx * 8 + 4];
#pragma unroll
            for (int i = 0; i < 8; i++)
#pragma unroll
                for (int j = 0; j < 8; j++)
                    acc[i][j] += a[i] * bb[j];
        }
        __syncthreads();
    }

    const float* brow = eb + (size_t)e * D_DIM;
#pragma unroll
    for (int i = 0; i < 8; i++) {
        const int m = rowBase + ty * 8 + i;
        if (m < n) {
            const int t = s_tok[ty * 8 + i];
#pragma unroll
            for (int j = 0; j < 8; j++) {
                const int c = colBase + tx * 8 + j;
                out[(size_t)t * D_DIM + c] = acc[i][j] + brow[c];
            }
        }
    }
}

// ---------------------------------------------------------------------------
// Launch
// ---------------------------------------------------------------------------
extern "C" void kernel_launch(void* const* d_in, const int* in_sizes, int n_in,
                              void* d_out, int out_size) {
    const float* X   = (const float*)d_in[0];  // hidden_states [4,4096,1024]
    const float* w1  = (const float*)d_in[1];  // [1024,512]
    const float* b1  = (const float*)d_in[2];  // [512]
    const float* w2  = (const float*)d_in[3];  // [512,8]
    const float* b2  = (const float*)d_in[4];  // [8]
    const float* eW  = (const float*)d_in[5];  // [8,1024,1024]
    const float* eb  = (const float*)d_in[6];  // [8,1024]
    float* out = (float*)d_out;                // [4,4096,1024]

    k_zero<<<1, 32>>>();
    k_gemm1<<<dim3(T_TOKENS / 128, M_DIM / 128), 256>>>(X, w1, b1);
    k_route<<<T_TOKENS / 8, 256>>>(w2, b2);
    k_scan<<<1, 1>>>();
    k_scatter<<<T_TOKENS / 256, 256>>>();
    k_expert<<<dim3(T_TOKENS / 128, D_DIM / 128, E_NUM), 256>>>(X, eW, eb, out);
}

// round 3
// speedup vs baseline: 1.5611x; 1.5611x over previous
#include <cuda_runtime.h>
#include <cuda_bf16.h>
#include <cstdint>

#define T_TOKENS 16384   // 4 * 4096
#define H_DIM    1024
#define M_DIM    512
#define E_NUM    8
#define D_DIM    1024

// ---------------------------------------------------------------------------
// Device scratch
// ---------------------------------------------------------------------------
__device__ float g_h[T_TOKENS * M_DIM];
__device__ int   g_top[T_TOKENS];
__device__ int   g_counts[E_NUM];
__device__ int   g_offsets[E_NUM + 1];
__device__ int   g_cursor[E_NUM];
__device__ int   g_perm[T_TOKENS];
__device__ __nv_bfloat16 g_Xhi[T_TOKENS * H_DIM];
__device__ __nv_bfloat16 g_Xlo[T_TOKENS * H_DIM];
__device__ __nv_bfloat16 g_Whi[E_NUM * D_DIM * H_DIM];  // expert_W^T [e][n][k]
__device__ __nv_bfloat16 g_Wlo[E_NUM * D_DIM * H_DIM];

// ---------------------------------------------------------------------------
// Helpers (base-feature PTX only: cp.async, ldmatrix, mma.sync)
// ---------------------------------------------------------------------------
__device__ __forceinline__ uint32_t smem_to_u32(const void* p) {
    uint32_t a;
    asm("{ .reg .u64 t; cvta.to.shared.u64 t, %1; cvt.u32.u64 %0, t; }" : "=r"(a) : "l"(p));
    return a;
}
#define SW128(o) ((o) ^ (((o) >> 3) & 0x70))

#define CP_ASYNC16(dst, src) \
    asm volatile("cp.async.cg.shared.global [%0], [%1], 16;" :: "r"(dst), "l"(src))
#define CP_COMMIT()  asm volatile("cp.async.commit_group;" ::: "memory")
#define CP_WAIT1()   asm volatile("cp.async.wait_group 1;" ::: "memory")
#define CP_WAIT0()   asm volatile("cp.async.wait_group 0;" ::: "memory")

__device__ __forceinline__ void ldsm4(uint32_t* r, uint32_t addr) {
    asm volatile("ldmatrix.sync.aligned.m8n8.x4.shared.b16 {%0,%1,%2,%3}, [%4];"
                 : "=r"(r[0]), "=r"(r[1]), "=r"(r[2]), "=r"(r[3]) : "r"(addr));
}
__device__ __forceinline__ void mma_bf16(float* c, const uint32_t* a, const uint32_t* b) {
    asm volatile("mma.sync.aligned.m16n8k16.row.col.f32.bf16.bf16.f32 "
                 "{%0,%1,%2,%3}, {%4,%5,%6,%7}, {%8,%9}, {%0,%1,%2,%3};"
                 : "+f"(c[0]), "+f"(c[1]), "+f"(c[2]), "+f"(c[3])
                 : "r"(a[0]), "r"(a[1]), "r"(a[2]), "r"(a[3]), "r"(b[0]), "r"(b[1]));
}

// ---------------------------------------------------------------------------
// K0: zero counters
// ---------------------------------------------------------------------------
__global__ void k_zero() {
    if (threadIdx.x < E_NUM) g_counts[threadIdx.x] = 0;
}

// ---------------------------------------------------------------------------
// Prep: split X into bf16 hi/lo
// ---------------------------------------------------------------------------
__global__ __launch_bounds__(256) void k_split_x(const float* __restrict__ X) {
    const size_t i = ((size_t)blockIdx.x * 256 + threadIdx.x) * 4;
    float4 v = *(const float4*)(X + i);
    __nv_bfloat16 h0 = __float2bfloat16(v.x), h1 = __float2bfloat16(v.y);
    __nv_bfloat16 h2 = __float2bfloat16(v.z), h3 = __float2bfloat16(v.w);
    __nv_bfloat16 l0 = __float2bfloat16(v.x - __bfloat162float(h0));
    __nv_bfloat16 l1 = __float2bfloat16(v.y - __bfloat162float(h1));
    __nv_bfloat16 l2 = __float2bfloat16(v.z - __bfloat162float(h2));
    __nv_bfloat16 l3 = __float2bfloat16(v.w - __bfloat162float(h3));
    *(__nv_bfloat162*)(g_Xhi + i)     = __nv_bfloat162(h0, h1);
    *(__nv_bfloat162*)(g_Xhi + i + 2) = __nv_bfloat162(h2, h3);
    *(__nv_bfloat162*)(g_Xlo + i)     = __nv_bfloat162(l0, l1);
    *(__nv_bfloat162*)(g_Xlo + i + 2) = __nv_bfloat162(l2, l3);
}

// ---------------------------------------------------------------------------
// Prep: transpose + split expert_W  (W[e][k][n] -> Wt[e][n][k], bf16 hi/lo)
// ---------------------------------------------------------------------------
__global__ __launch_bounds__(256) void k_split_w(const float* __restrict__ W) {
    __shared__ float tile[32][33];
    const int e = blockIdx.z;
    const int kb = blockIdx.x * 32, nb = blockIdx.y * 32;
    const int tx = threadIdx.x & 31, ty = threadIdx.x >> 5;
    const float* Wp = W + ((size_t)e << 20);
#pragma unroll
    for (int i = 0; i < 32; i += 8)
        tile[ty + i][tx] = Wp[(size_t)(kb + ty + i) * D_DIM + nb + tx];
    __syncthreads();
#pragma unroll
    for (int i = 0; i < 32; i += 8) {
        const float x = tile[tx][ty + i];
        const __nv_bfloat16 hi = __float2bfloat16(x);
        const __nv_bfloat16 lo = __float2bfloat16(x - __bfloat162float(hi));
        const size_t o = ((size_t)e << 20) + (size_t)(nb + ty + i) * H_DIM + kb + tx;
        g_Whi[o] = hi;
        g_Wlo[o] = lo;
    }
}

// ---------------------------------------------------------------------------
// K1: router hidden (exact fp32 SIMT) h = relu(X @ w1 + b1)
// ---------------------------------------------------------------------------
__global__ __launch_bounds__(256) void k_gemm1(const float* __restrict__ X,
                                               const float* __restrict__ W,
                                               const float* __restrict__ b1) {
    __shared__ float As[8][128];
    __shared__ float Bs[8][128];
    const int tid = threadIdx.x;
    const int tx = tid & 15, ty = tid >> 4;
    const int rowBase = blockIdx.x * 128;
    const int colBase = blockIdx.y * 128;
    const int aRow = tid >> 1, aK = (tid & 1) * 4;
    const int bRow = tid >> 5, bCol = (tid & 31) * 4;

    float acc[8][8] = {};
    for (int k0 = 0; k0 < H_DIM; k0 += 8) {
        float4 av = *(const float4*)&X[(size_t)(rowBase + aRow) * H_DIM + k0 + aK];
        As[aK + 0][aRow] = av.x;
        As[aK + 1][aRow] = av.y;
        As[aK + 2][aRow] = av.z;
        As[aK + 3][aRow] = av.w;
        *(float4*)&Bs[bRow][bCol] =
            *(const float4*)&W[(size_t)(k0 + bRow) * M_DIM + colBase + bCol];
        __syncthreads();
#pragma unroll
        for (int kk = 0; kk < 8; kk++) {
            float a[8], bb[8];
            *(float4*)&a[0]  = *(const float4*)&As[kk][ty * 8];
            *(float4*)&a[4]  = *(const float4*)&As[kk][ty * 8 + 4];
            *(float4*)&bb[0] = *(const float4*)&Bs[kk][tx * 8];
            *(float4*)&bb[4] = *(const float4*)&Bs[kk][tx * 8 + 4];
#pragma unroll
            for (int i = 0; i < 8; i++)
#pragma unroll
                for (int j = 0; j < 8; j++)
                    acc[i][j] += a[i] * bb[j];
        }
        __syncthreads();
    }
#pragma unroll
    for (int i = 0; i < 8; i++) {
        const int r = rowBase + ty * 8 + i;
#pragma unroll
        for (int j = 0; j < 8; j++) {
            const int c = colBase + tx * 8 + j;
            float v = acc[i][j] + b1[c];
            g_h[(size_t)r * M_DIM + c] = v > 0.f ? v : 0.f;
        }
    }
}

// ---------------------------------------------------------------------------
// K2: routing scores + argmax + histogram (fp32 exact)
// ---------------------------------------------------------------------------
__global__ __launch_bounds__(256) void k_route(const float* __restrict__ w2,
                                               const float* __restrict__ b2) {
    __shared__ float s_w2[M_DIM * E_NUM];
    for (int i = threadIdx.x; i < M_DIM * E_NUM; i += 256) s_w2[i] = w2[i];
    __syncthreads();

    const int warp = threadIdx.x >> 5, lane = threadIdx.x & 31;
    const int t = blockIdx.x * 8 + warp;
    float acc[E_NUM] = {};
    const float* hrow = &g_h[(size_t)t * M_DIM];
    for (int m = lane; m < M_DIM; m += 32) {
        const float hv = hrow[m];
#pragma unroll
        for (int e = 0; e < E_NUM; e++) acc[e] += hv * s_w2[m * E_NUM + e];
    }
#pragma unroll
    for (int e = 0; e < E_NUM; e++) {
        float v = acc[e];
#pragma unroll
        for (int off = 16; off > 0; off >>= 1) v += __shfl_down_sync(0xffffffffu, v, off);
        acc[e] = v;
    }
    if (lane == 0) {
        float best = acc[0] + b2[0];
        int bi = 0;
#pragma unroll
        for (int e = 1; e < E_NUM; e++) {
            const float v = acc[e] + b2[e];
            if (v > best) { best = v; bi = e; }
        }
        g_top[t] = bi;
        atomicAdd(&g_counts[bi], 1);
    }
}

__global__ void k_scan() {
    if (threadIdx.x == 0) {
        int off = 0;
        for (int e = 0; e < E_NUM; e++) {
            g_offsets[e] = off;
            g_cursor[e]  = off;
            off += g_counts[e];
        }
        g_offsets[E_NUM] = off;
    }
}

__global__ void k_scatter() {
    const int t = blockIdx.x * blockDim.x + threadIdx.x;
    if (t < T_TOKENS) {
        const int e = g_top[t];
        const int pos = atomicAdd(&g_cursor[e], 1);
        g_perm[pos] = t;
    }
}

// ---------------------------------------------------------------------------
// K5: expert GEMM, mma.sync bf16 hi/lo split (3 products, fp32 accumulate)
// CTA tile 128x128, K-chunk 64, cp.async double buffered, SW128 smem.
// 8 warps = 4(m) x 2(n); warp tile 32x64.
// smem: [64] s_tok (512B), [576] s_bias (512B), [2048] 2 x 64KB tile buffers
//   per buffer: Ahi 16K | Alo 16K | Bhi 16K | Blo 16K  (rows of 128B, SW128)
// ---------------------------------------------------------------------------
#define SMEM_TILES_OFF 2048
#define SMEM_BYTES (SMEM_TILES_OFF + 2 * 65536)

__global__ __launch_bounds__(256) void k_expert_hmma(float* __restrict__ out,
                                                     const float* __restrict__ eb) {
    const int e = blockIdx.z;
    const int off = g_offsets[e];
    const int n = g_offsets[e + 1] - off;
    const int rowBase = blockIdx.x * 128;
    if (rowBase >= n) return;

    extern __shared__ char smem[];
    const uint32_t sb = smem_to_u32(smem);
    const int tid = threadIdx.x;
    const int lane = tid & 31;
    const int wid = tid >> 5;
    const int warp_m = wid & 3;       // m offset = warp_m*32
    const int warp_n = wid >> 2;      // n offset = warp_n*64
    const int colBase = blockIdx.y * 128;

    int*   s_tok  = (int*)(smem + 64);
    float* s_bias = (float*)(smem + 576);
    if (tid < 128) {
        const int m = rowBase + tid;
        s_tok[tid]  = g_perm[off + (m < n ? m : 0)];
        s_bias[tid] = eb[(size_t)e * D_DIM + colBase + tid];
    }
    __syncthreads();

    // cp.async assignment: 2 threads per row, each 64B (4 x 16B) per array
    const int lr = tid >> 1;
    const int lh = tid & 1;
    const __nv_bfloat16* aHi = g_Xhi + (size_t)s_tok[lr] * H_DIM + lh * 32;
    const __nv_bfloat16* aLo = g_Xlo + (size_t)s_tok[lr] * H_DIM + lh * 32;
    const size_t wOff = ((size_t)e << 20) + (size_t)(colBase + lr) * H_DIM + lh * 32;
    const __nv_bfloat16* bHi = g_Whi + wOff;
    const __nv_bfloat16* bLo = g_Wlo + wOff;

    auto load_chunk = [&](int c) {
        const uint32_t tb = sb + SMEM_TILES_OFF + (uint32_t)(c & 1) * 65536;
        const int kElem = c * 64;
#pragma unroll
        for (int j = 0; j < 4; j++) {
            const uint32_t o = SW128((uint32_t)(lr * 128 + lh * 64 + j * 16));
            CP_ASYNC16(tb + o,         (const char*)(aHi + kElem) + j * 16);
            CP_ASYNC16(tb + 16384 + o, (const char*)(aLo + kElem) + j * 16);
            CP_ASYNC16(tb + 32768 + o, (const char*)(bHi + kElem) + j * 16);
            CP_ASYNC16(tb + 49152 + o, (const char*)(bLo + kElem) + j * 16);
        }
    };

    float acc[2][8][4];
#pragma unroll
    for (int mi = 0; mi < 2; mi++)
#pragma unroll
        for (int ni = 0; ni < 8; ni++)
#pragma unroll
            for (int j = 0; j < 4; j++) acc[mi][ni][j] = 0.f;

    load_chunk(0);
    CP_COMMIT();

    for (int c = 0; c < 16; c++) {
        if (c + 1 < 16) { load_chunk(c + 1); CP_COMMIT(); CP_WAIT1(); }
        else            { CP_WAIT0(); }
        __syncthreads();

        const uint32_t tb = sb + SMEM_TILES_OFF + (uint32_t)(c & 1) * 65536;
#pragma unroll
        for (int ks = 0; ks < 4; ks++) {
            uint32_t aH[2][4], aL[2][4];
#pragma unroll
            for (int mi = 0; mi < 2; mi++) {
                const int row = warp_m * 32 + mi * 16 + (lane & 15);
                const uint32_t o =
                    (uint32_t)(row * 128 + ((ks * 32 + (lane >> 4) * 16) ^ ((row & 7) << 4)));
                ldsm4(aH[mi], tb + o);
                ldsm4(aL[mi], tb + 16384 + o);
            }
            uint32_t bH[8][2], bL[8][2];
#pragma unroll
            for (int nt = 0; nt < 4; nt++) {
                const int row = warp_n * 64 + nt * 16 + ((lane >> 4) << 3) + (lane & 7);
                const uint32_t o =
                    (uint32_t)(row * 128 +
                               ((ks * 32 + ((lane >> 3) & 1) * 16) ^ ((row & 7) << 4)));
                uint32_t r4[4];
                ldsm4(r4, tb + 32768 + o);
                bH[nt * 2][0] = r4[0]; bH[nt * 2][1] = r4[1];
                bH[nt * 2 + 1][0] = r4[2]; bH[nt * 2 + 1][1] = r4[3];
                ldsm4(r4, tb + 49152 + o);
                bL[nt * 2][0] = r4[0]; bL[nt * 2][1] = r4[1];
                bL[nt * 2 + 1][0] = r4[2]; bL[nt * 2 + 1][1] = r4[3];
            }
#pragma unroll
            for (int mi = 0; mi < 2; mi++)
#pragma unroll
                for (int ni = 0; ni < 8; ni++) {
                    mma_bf16(acc[mi][ni], aH[mi], bH[ni]);
                    mma_bf16(acc[mi][ni], aH[mi], bL[ni]);
                    mma_bf16(acc[mi][ni], aL[mi], bH[ni]);
                }
        }
        __syncthreads();
    }

    // Epilogue: acc fragment (mi,ni): rows warp_m*32+mi*16+{t/4, t/4+8},
    //           cols warp_n*64+ni*8+(t%4)*2 + {0,1}
#pragma unroll
    for (int mi = 0; mi < 2; mi++) {
        const int r0 = warp_m * 32 + mi * 16 + (lane >> 2);
        const int r1 = r0 + 8;
        const bool v0 = (rowBase + r0) < n;
        const bool v1 = (rowBase + r1) < n;
        float* o0 = out + (size_t)s_tok[r0] * D_DIM + colBase;
        float* o1 = out + (size_t)s_tok[r1] * D_DIM + colBase;
#pragma unroll
        for (int ni = 0; ni < 8; ni++) {
            const int col = warp_n * 64 + ni * 8 + (lane & 3) * 2;
            if (v0) {
                float2 w{acc[mi][ni][0] + s_bias[col], acc[mi][ni][1] + s_bias[col + 1]};
                *(float2*)(o0 + col) = w;
            }
            if (v1) {
                float2 w{acc[mi][ni][2] + s_bias[col], acc[mi][ni][3] + s_bias[col + 1]};
                *(float2*)(o1 + col) = w;
            }
        }
    }
}

// ---------------------------------------------------------------------------
// Launch
// ---------------------------------------------------------------------------
extern "C" void kernel_launch(void* const* d_in, const int* in_sizes, int n_in,
                              void* d_out, int out_size) {
    const float* X  = (const float*)d_in[0];
    const float* w1 = (const float*)d_in[1];
    const float* b1 = (const float*)d_in[2];
    const float* w2 = (const float*)d_in[3];
    const float* b2 = (const float*)d_in[4];
    const float* eW = (const float*)d_in[5];
    const float* eb = (const float*)d_in[6];
    float* out = (float*)d_out;

    static bool attr_set = false;
    if (!attr_set) {
        cudaFuncSetAttribute(k_expert_hmma, cudaFuncAttributeMaxDynamicSharedMemorySize,
                             SMEM_BYTES);
        attr_set = true;
    }

    k_zero<<<1, 32>>>();
    k_split_x<<<(T_TOKENS * H_DIM) / (256 * 4), 256>>>(X);
    k_split_w<<<dim3(H_DIM / 32, D_DIM / 32, E_NUM), 256>>>(eW);
    k_gemm1<<<dim3(T_TOKENS / 128, M_DIM / 128), 256>>>(X, w1, b1);
    k_route<<<T_TOKENS / 8, 256>>>(w2, b2);
    k_scan<<<1, 1>>>();
    k_scatter<<<T_TOKENS / 256, 256>>>();
    k_expert_hmma<<<dim3(T_TOKENS / 128, D_DIM / 128, E_NUM), 256, SMEM_BYTES>>>(out, eb);
}